// round 16
// baseline (speedup 1.0000x reference)
#include <cuda_runtime.h>
#include <math.h>

// Problem shape (fixed by the dataset):
//   t: [16, 256, 128, 128] fp32
//   w_reduce: [256, 1024], b_reduce: [256]
//   w_expand: [1024, 256], b_expand: [1024]
// Output: same shape as t.

#define NB   16
#define NC   256
#define NSQ  256
#define NC4  1024         // 4*C
#define IMG_F4 4096       // 128*128/4 float4 per (b,c) image

#define FC1_CTAS 32
#define FC2_CTAS 128
#define FC_CTAS  (FC1_CTAS + FC2_CTAS)   // 160

// Scratch (allocation-free rule: __device__ globals)
__device__ float g_means[NB * NC4];   // layout: [b][q*C + c]
__device__ float g_z    [NB * NSQ];   // layout: [b][j]
__device__ float g_gate [NB * NC4];   // layout: [b][q*C + c]
__device__ int   g_fc1_done;          // counts fc1 CTAs (target 32)
__device__ int   g_fc2_done;          // counts fc2 CTAs (target 128)

// ---------------------------------------------------------------------------
// Kernel 1: per-(b,c) quadrant means. (R9-proven: ~41.5us @ 82.9% DRAM.)
// Block 0 also zeroes the FC flags — this kernel completes before any flag
// use in the successor (its gridsync), so ordering is guaranteed per replay.
// ---------------------------------------------------------------------------
__global__ __launch_bounds__(256) void quad_means_kernel(const float* __restrict__ t)
{
    const int img = blockIdx.x;                 // b*C + c
    const int tid = threadIdx.x;

    if (img == 0 && tid == 0) {
        g_fc1_done = 0;
        g_fc2_done = 0;
    }

    const float4* __restrict__ p =
        reinterpret_cast<const float4*>(t) + (size_t)img * IMG_F4;

    float topS = 0.f, botS = 0.f;
#pragma unroll
    for (int k = 0; k < 16; ++k) {
        float4 v = p[tid + k * 256];
        float s = (v.x + v.y) + (v.z + v.w);
        if (k < 8) topS += s; else botS += s;
    }

    const bool right = (tid & 31) >= 16;

    __shared__ float sm[4 * 256];
    sm[0 * 256 + tid] = right ? 0.f : topS;   // q0: top-left
    sm[1 * 256 + tid] = right ? topS : 0.f;   // q1: top-right
    sm[2 * 256 + tid] = right ? 0.f : botS;   // q2: bot-left
    sm[3 * 256 + tid] = right ? botS : 0.f;   // q3: bot-right
    __syncthreads();

#pragma unroll
    for (int st = 128; st > 0; st >>= 1) {
        if (tid < st) {
#pragma unroll
            for (int q = 0; q < 4; ++q)
                sm[q * 256 + tid] += sm[q * 256 + tid + st];
        }
        __syncthreads();
    }

    if (tid < 4) {
        const int b = img >> 8;
        const int c = img & 255;
        g_means[b * NC4 + tid * NC + c] = sm[tid * 256] * (1.0f / 4096.0f);
    }
}

// ---------------------------------------------------------------------------
// Kernel 2 (apply_fused): FC chain + gated multiply in ONE kernel.
//  - blocks 0..31   : fc1 (z = mish(means@Wr^T+br)), then apply
//  - blocks 32..159 : fc2 (gate = sigmoid(z@We^T+be)) after fc1 flag, then apply
//  - all other blocks: spin briefly on fc2 flag, then apply
// Wave-1 holds >= 6*148 = 888 lowest-blockIdx CTAs, so all 160 FC blocks are
// resident in wave 1 and spinners cannot starve them (FC waits on nothing
// except the fc1->fc2 flag, whose producers are also wave-1 resident).
// Memory path identical to R9's apply_gate: reverse traversal, 4 float4 per
// thread strided 256 in a 1024-f4 block, default loads, streaming stores,
// PDL prologue prefetch of t.
// ---------------------------------------------------------------------------
__global__ __launch_bounds__(256, 6) void apply_fused_kernel(
    const float* __restrict__ t, float* __restrict__ out,
    const float* __restrict__ w_reduce, const float* __restrict__ b_reduce,
    const float* __restrict__ w_expand, const float* __restrict__ b_expand)
{
    const int tid  = threadIdx.x;
    const int warp = tid >> 5;
    const int lane = tid & 31;

    const int cta  = gridDim.x - 1 - blockIdx.x;        // descending memory order
    const int base = cta * 1024 + tid;                  // float4 index

    const float4* __restrict__ tp = reinterpret_cast<const float4*>(t);
    float4* __restrict__ op       = reinterpret_cast<float4*>(out);

    // ---- PDL prologue: prefetch t (independent of predecessor) ----
    float4 v0 = tp[base];
    float4 v1 = tp[base + 256];
    float4 v2 = tp[base + 512];
    float4 v3 = tp[base + 768];

    // ---- wait for quad_means (means + zeroed flags valid after this) ----
    cudaGridDependencySynchronize();

    if (blockIdx.x < FC1_CTAS) {
        // ================= fc1: warp owns output j =================
        const int j = blockIdx.x * 8 + warp;
        const float4* __restrict__ wr4 =
            reinterpret_cast<const float4*>(w_reduce + (size_t)j * NC4);
        const float4* __restrict__ m4 =
            reinterpret_cast<const float4*>(g_means);

        float acc[NB];
#pragma unroll
        for (int b = 0; b < NB; ++b) {
            float a = 0.f;
#pragma unroll
            for (int i = 0; i < 8; ++i) {
                float4 wv = __ldg(wr4 + lane + 32 * i);
                float4 mv = __ldg(m4 + b * 256 + lane + 32 * i);
                a += wv.x * mv.x + wv.y * mv.y + wv.z * mv.z + wv.w * mv.w;
            }
            acc[b] = a;
        }
#pragma unroll
        for (int o = 16; o > 0; o >>= 1) {
#pragma unroll
            for (int b = 0; b < NB; ++b)
                acc[b] += __shfl_xor_sync(0xFFFFFFFFu, acc[b], o);
        }
        if (lane == 0) {
            const float bj = b_reduce[j];
#pragma unroll
            for (int b = 0; b < NB; ++b) {
                float x = acc[b] + bj;
                float sp = (x > 20.0f) ? x : log1pf(expf(x));
                g_z[b * NSQ + j] = x * tanhf(sp);
            }
        }
        __syncthreads();
        if (tid == 0) {
            __threadfence();
            atomicAdd(&g_fc1_done, 1);
        }
    } else if (blockIdx.x < FC_CTAS) {
        // ================= fc2: warp owns output j =================
        const int j = (blockIdx.x - FC1_CTAS) * 8 + warp;
        const float4* __restrict__ we4 =
            reinterpret_cast<const float4*>(w_expand + (size_t)j * NSQ);
        float4 w0 = __ldg(we4 + lane);
        float4 w1 = __ldg(we4 + lane + 32);
        const float bj = b_expand[j];

        // wait for fc1
        if (tid == 0) {
            volatile int* f = &g_fc1_done;
            while (*f < FC1_CTAS) __nanosleep(64);
        }
        __syncthreads();
        __threadfence();

        const float4* __restrict__ z4 = reinterpret_cast<const float4*>(g_z);
        float acc[NB];
#pragma unroll
        for (int b = 0; b < NB; ++b) {
            float4 z0 = __ldg(z4 + b * 64 + lane);
            float4 z1 = __ldg(z4 + b * 64 + lane + 32);
            acc[b] = w0.x * z0.x + w0.y * z0.y + w0.z * z0.z + w0.w * z0.w
                   + w1.x * z1.x + w1.y * z1.y + w1.z * z1.z + w1.w * z1.w;
        }
#pragma unroll
        for (int o = 16; o > 0; o >>= 1) {
#pragma unroll
            for (int b = 0; b < NB; ++b)
                acc[b] += __shfl_xor_sync(0xFFFFFFFFu, acc[b], o);
        }
        if (lane == 0) {
#pragma unroll
            for (int b = 0; b < NB; ++b)
                g_gate[b * NC4 + j] = 1.0f / (1.0f + expf(-acc[b] - bj));
        }
        __syncthreads();
        if (tid == 0) {
            __threadfence();
            atomicAdd(&g_fc2_done, 1);
        }
    }

    // ================= apply: everyone waits for the gate =================
    if (tid == 0) {
        volatile int* f = &g_fc2_done;
        while (*f < FC2_CTAS) __nanosleep(64);
    }
    __syncthreads();
    __threadfence();

    const int img    = base >> 12;
    const int within = base & (IMG_F4 - 1);
    const int row    = within >> 5;
    const int col4   = within & 31;
    const int q      = ((row >= 64) ? 2 : 0) | ((col4 >= 16) ? 1 : 0);
    const int b      = img >> 8;
    const int c      = img & 255;

    const float gv = __ldg(&g_gate[b * NC4 + q * NC + c]);

    v0.x *= gv; v0.y *= gv; v0.z *= gv; v0.w *= gv;
    v1.x *= gv; v1.y *= gv; v1.z *= gv; v1.w *= gv;
    v2.x *= gv; v2.y *= gv; v2.z *= gv; v2.w *= gv;
    v3.x *= gv; v3.y *= gv; v3.z *= gv; v3.w *= gv;

    __stcs(op + base,       v0);
    __stcs(op + base + 256, v1);
    __stcs(op + base + 512, v2);
    __stcs(op + base + 768, v3);
}

// ---------------------------------------------------------------------------
static void launch_pdl(void* func, dim3 grid, dim3 block, void** args)
{
    cudaLaunchConfig_t cfg = {};
    cfg.gridDim  = grid;
    cfg.blockDim = block;
    cudaLaunchAttribute attr[1];
    attr[0].id = cudaLaunchAttributeProgrammaticStreamSerialization;
    attr[0].val.programmaticStreamSerializationAllowed = 1;
    cfg.attrs = attr;
    cfg.numAttrs = 1;
    cudaLaunchKernelExC(&cfg, func, args);
}

extern "C" void kernel_launch(void* const* d_in, const int* in_sizes, int n_in,
                              void* d_out, int out_size)
{
    const float* t        = (const float*)d_in[0];
    const float* w_reduce = (const float*)d_in[1];
    const float* b_reduce = (const float*)d_in[2];
    const float* w_expand = (const float*)d_in[3];
    const float* b_expand = (const float*)d_in[4];
    float* out            = (float*)d_out;

    // Pass 1: quadrant means (4096 CTAs) — R9-proven, ~41.5us @ 82.9% DRAM
    quad_means_kernel<<<NB * NC, 256>>>(t);

    // Pass 2: fused FC + gated multiply, single PDL handoff.
    {
        void* args[] = {(void*)&t, (void*)&out,
                        (void*)&w_reduce, (void*)&b_reduce,
                        (void*)&w_expand, (void*)&b_expand};
        const int total_f4 = NB * NC * IMG_F4;   // 16777216
        dim3 grid(total_f4 / 1024);              // 16384
        launch_pdl((void*)apply_fused_kernel, grid, dim3(256), args);
    }
}

// round 17
// speedup vs baseline: 1.5057x; 1.5057x over previous
#include <cuda_runtime.h>
#include <math.h>

// Problem shape (fixed by the dataset):
//   t: [16, 256, 128, 128] fp32
//   w_reduce: [256, 1024], b_reduce: [256]
//   w_expand: [1024, 256], b_expand: [1024]
// Output: same shape as t.
//
// Final configuration (empirical optimum over 16 rounds):
//   quad_means (41.5us @ 82.9% DRAM) -> fc1 -> fc2 -> apply_gate
//   (75.7us @ ~80% DRAM), PDL-chained with independent work hoisted into
//   each kernel's pre-gridsync prologue; apply_gate traverses in reverse to
//   consume quad_means' L2-resident tail. Total ~129us vs ~123us traffic
//   floor (805MB @ 6.5TB/s measured ceiling).

#define NB   16
#define NC   256
#define NSQ  256
#define NC4  1024         // 4*C
#define IMG_F4 4096       // 128*128/4 float4 per (b,c) image

// Scratch (allocation-free rule: __device__ globals)
__device__ float g_means[NB * NC4];   // layout: [b][q*C + c]
__device__ float g_z    [NB * NSQ];   // layout: [b][j]
__device__ float g_gate [NB * NC4];   // layout: [b][q*C + c]

// ---------------------------------------------------------------------------
// Kernel 1: per-(b,c) quadrant means. One CTA per image; 256 threads x 16
// fully-coalesced float4 loads; lane fixes column quadrant, k fixes row
// quadrant; 4-way shared tree reduction. Default (allocating) loads on
// purpose: the tail of t stays L2-resident for apply_gate's reverse reads.
// ---------------------------------------------------------------------------
__global__ __launch_bounds__(256) void quad_means_kernel(const float* __restrict__ t)
{
    const int img = blockIdx.x;                 // b*C + c
    const int tid = threadIdx.x;
    const float4* __restrict__ p =
        reinterpret_cast<const float4*>(t) + (size_t)img * IMG_F4;

    float topS = 0.f, botS = 0.f;
#pragma unroll
    for (int k = 0; k < 16; ++k) {
        float4 v = p[tid + k * 256];
        float s = (v.x + v.y) + (v.z + v.w);
        if (k < 8) topS += s; else botS += s;
    }

    const bool right = (tid & 31) >= 16;

    __shared__ float sm[4 * 256];
    sm[0 * 256 + tid] = right ? 0.f : topS;   // q0: top-left
    sm[1 * 256 + tid] = right ? topS : 0.f;   // q1: top-right
    sm[2 * 256 + tid] = right ? 0.f : botS;   // q2: bot-left
    sm[3 * 256 + tid] = right ? botS : 0.f;   // q3: bot-right
    __syncthreads();

#pragma unroll
    for (int st = 128; st > 0; st >>= 1) {
        if (tid < st) {
#pragma unroll
            for (int q = 0; q < 4; ++q)
                sm[q * 256 + tid] += sm[q * 256 + tid + st];
        }
        __syncthreads();
    }

    if (tid < 4) {
        const int b = img >> 8;
        const int c = img & 255;
        g_means[b * NC4 + tid * NC + c] = sm[tid * 256] * (1.0f / 4096.0f);
    }
}

// ---------------------------------------------------------------------------
// Kernel 2a: z = mish(means @ w_reduce^T + b_reduce).
// PDL: weight rows loaded into registers BEFORE the dependency sync (they
// don't depend on quad_means), overlapping with quad_means' tail.
// Grid 32 x 256. Warp w owns output j = cta*8 + w; 16 per-batch accumulators,
// interleaved shfl reduce (pipelines the 5-deep SHFL latency chains).
// ---------------------------------------------------------------------------
__global__ __launch_bounds__(256) void fc1_kernel(
    const float* __restrict__ w_reduce, const float* __restrict__ b_reduce)
{
    const int tid  = threadIdx.x;
    const int warp = tid >> 5;
    const int lane = tid & 31;

    const int j = blockIdx.x * 8 + warp;

    // ---- PDL prologue: independent of predecessor ----
    const float4* __restrict__ w =
        reinterpret_cast<const float4*>(w_reduce + (size_t)j * NC4);
    float4 wr[8];
#pragma unroll
    for (int i = 0; i < 8; ++i)
        wr[i] = w[lane + 32 * i];
    const float bj = b_reduce[j];

    // ---- wait for quad_means ----
    cudaGridDependencySynchronize();

    __shared__ float4 sm_m[NB * 256];     // all means: 16 x 1024 fp32 = 64KB
    {
        const float4* __restrict__ mp = reinterpret_cast<const float4*>(g_means);
#pragma unroll
        for (int i = 0; i < 16; ++i)
            sm_m[tid + i * 256] = mp[tid + i * 256];
    }
    __syncthreads();

    float acc[NB];
#pragma unroll
    for (int b = 0; b < NB; ++b) {
        float a = 0.f;
#pragma unroll
        for (int i = 0; i < 8; ++i) {
            float4 mv = sm_m[b * 256 + lane + 32 * i];
            a += wr[i].x * mv.x + wr[i].y * mv.y + wr[i].z * mv.z + wr[i].w * mv.w;
        }
        acc[b] = a;
    }

    // interleaved butterfly reduce: 16 independent chains pipeline SHFL latency
#pragma unroll
    for (int o = 16; o > 0; o >>= 1) {
#pragma unroll
        for (int b = 0; b < NB; ++b)
            acc[b] += __shfl_xor_sync(0xFFFFFFFFu, acc[b], o);
    }

    if (lane == 0) {
#pragma unroll
        for (int b = 0; b < NB; ++b) {
            float x = acc[b] + bj;
            float sp = (x > 20.0f) ? x : log1pf(expf(x));
            g_z[b * NSQ + j] = x * tanhf(sp);
        }
    }
}

// ---------------------------------------------------------------------------
// Kernel 2b: gate = sigmoid(z @ w_expand^T + b_expand).
// Grid 128 x 256: warp-per-output (1024 warps), 16 per-batch accumulators,
// interleaved reduce. Weight rows loaded pre-sync (PDL prologue).
// ---------------------------------------------------------------------------
__global__ __launch_bounds__(256) void fc2_kernel(
    const float* __restrict__ w_expand, const float* __restrict__ b_expand)
{
    const int tid  = threadIdx.x;
    const int warp = tid >> 5;
    const int lane = tid & 31;

    const int j = blockIdx.x * 8 + warp;

    // ---- PDL prologue ----
    const float4* __restrict__ w =
        reinterpret_cast<const float4*>(w_expand + (size_t)j * NSQ);
    float4 w0 = w[lane];
    float4 w1 = w[lane + 32];
    const float bj = b_expand[j];

    // ---- wait for fc1 ----
    cudaGridDependencySynchronize();

    __shared__ float4 sm_z[NB * 64];      // all z: 16 x 256 fp32 = 16KB
    {
        const float4* __restrict__ zp = reinterpret_cast<const float4*>(g_z);
#pragma unroll
        for (int i = 0; i < 4; ++i)
            sm_z[tid + i * 256] = zp[tid + i * 256];
    }
    __syncthreads();

    float acc[NB];
#pragma unroll
    for (int b = 0; b < NB; ++b) {
        float4 z0 = sm_z[b * 64 + lane];
        float4 z1 = sm_z[b * 64 + lane + 32];
        acc[b] = w0.x * z0.x + w0.y * z0.y + w0.z * z0.z + w0.w * z0.w
               + w1.x * z1.x + w1.y * z1.y + w1.z * z1.z + w1.w * z1.w;
    }

#pragma unroll
    for (int o = 16; o > 0; o >>= 1) {
#pragma unroll
        for (int b = 0; b < NB; ++b)
            acc[b] += __shfl_xor_sync(0xFFFFFFFFu, acc[b], o);
    }

    if (lane == 0) {
#pragma unroll
        for (int b = 0; b < NB; ++b)
            g_gate[b * NC4 + j] = 1.0f / (1.0f + expf(-acc[b] - bj));
    }
}

// ---------------------------------------------------------------------------
// Kernel 3: out = t * gate. 4 float4 per thread, strided by 256 within a
// 1024-float4 block. 1024 | 4096 so a CTA never crosses an image; the four
// accesses of one thread share (b, c, quadrant). PDL: the four t loads are
// issued BEFORE the dependency sync (t doesn't depend on the gate), so
// wave-1 CTAs prefetch t while fc1/fc2 are still running.
// REVERSE traversal: first waves read the highest addresses — the tail of t
// that quad_means left L2-resident (wallclock win not visible under ncu's
// cache-control flush). Streaming stores limit pollution.
// ---------------------------------------------------------------------------
__global__ __launch_bounds__(256) void apply_gate_kernel(
    const float* __restrict__ t, float* __restrict__ out)
{
    const int cta  = gridDim.x - 1 - blockIdx.x;        // descending order
    const int base = cta * 1024 + threadIdx.x;          // float4 index

    const float4* __restrict__ tp = reinterpret_cast<const float4*>(t);
    float4* __restrict__ op       = reinterpret_cast<float4*>(out);

    // ---- PDL prologue: prefetch t (independent of gate) ----
    float4 v0 = tp[base];
    float4 v1 = tp[base + 256];
    float4 v2 = tp[base + 512];
    float4 v3 = tp[base + 768];

    // ---- wait for fc2 ----
    cudaGridDependencySynchronize();

    const int img    = base >> 12;
    const int within = base & (IMG_F4 - 1);
    const int row    = within >> 5;
    const int col4   = within & 31;
    const int q      = ((row >= 64) ? 2 : 0) | ((col4 >= 16) ? 1 : 0);
    const int b      = img >> 8;
    const int c      = img & 255;

    const float gv = __ldg(&g_gate[b * NC4 + q * NC + c]);

    v0.x *= gv; v0.y *= gv; v0.z *= gv; v0.w *= gv;
    v1.x *= gv; v1.y *= gv; v1.z *= gv; v1.w *= gv;
    v2.x *= gv; v2.y *= gv; v2.z *= gv; v2.w *= gv;
    v3.x *= gv; v3.y *= gv; v3.z *= gv; v3.w *= gv;

    __stcs(op + base,       v0);
    __stcs(op + base + 256, v1);
    __stcs(op + base + 512, v2);
    __stcs(op + base + 768, v3);
}

// ---------------------------------------------------------------------------
static void launch_pdl(void* func, dim3 grid, dim3 block, void** args)
{
    cudaLaunchConfig_t cfg = {};
    cfg.gridDim  = grid;
    cfg.blockDim = block;
    cudaLaunchAttribute attr[1];
    attr[0].id = cudaLaunchAttributeProgrammaticStreamSerialization;
    attr[0].val.programmaticStreamSerializationAllowed = 1;
    cfg.attrs = attr;
    cfg.numAttrs = 1;
    cudaLaunchKernelExC(&cfg, func, args);
}

extern "C" void kernel_launch(void* const* d_in, const int* in_sizes, int n_in,
                              void* d_out, int out_size)
{
    const float* t        = (const float*)d_in[0];
    const float* w_reduce = (const float*)d_in[1];
    const float* b_reduce = (const float*)d_in[2];
    const float* w_expand = (const float*)d_in[3];
    const float* b_expand = (const float*)d_in[4];
    float* out            = (float*)d_out;

    // Pass 1: quadrant means (4096 CTAs) — measured 41.5us @ 82.9% DRAM
    quad_means_kernel<<<NB * NC, 256>>>(t);

    // FC chain + apply, PDL-chained so launch gaps overlap predecessors.
    {
        void* args[] = {(void*)&w_reduce, (void*)&b_reduce};
        launch_pdl((void*)fc1_kernel, dim3(32), dim3(256), args);
    }
    {
        void* args[] = {(void*)&w_expand, (void*)&b_expand};
        launch_pdl((void*)fc2_kernel, dim3(128), dim3(256), args);
    }
    {
        void* args[] = {(void*)&t, (void*)&out};
        const int total_f4 = NB * NC * IMG_F4;   // 16777216
        dim3 grid(total_f4 / 1024);              // 16384
        launch_pdl((void*)apply_gate_kernel, grid, dim3(256), args);
    }
}